// round 2
// baseline (speedup 1.0000x reference)
#include <cuda_runtime.h>
#include <math.h>

// Problem dims
#define T_ 512
#define B_ 64
#define F_ 256
#define H_ 1024
#define C_ 257

// ---------------------------------------------------------------------------
// Scratch (device globals; no allocation allowed)
// ---------------------------------------------------------------------------
__device__ float g_gates[(size_t)T_ * H_ * B_ * 4]; // [t][j][b][g]  (g = f,i,o,c)
__device__ float g_hT[(size_t)T_ * H_ * B_];        // [t][j][b]
__device__ float g_cT[(size_t)H_ * B_];             // [j][b]
__device__ float g_Wpk[(size_t)128 * H_ * 32];      // [jt][k(1024)][r(32)] r = jj*4+g
__device__ float g_WXpk[(size_t)128 * F_ * 32];     // [jt][k(256)][r(32)]
__device__ float g_FCpk[(size_t)9 * H_ * 32];       // [ct][k(1024)][cc(32)] zero-padded c>=257
__device__ float g_xT[(size_t)T_ * F_ * B_];        // [t][k][b]

// ---------------------------------------------------------------------------
// f32x2 packed-FMA helpers (Blackwell FFMA2 — only reachable via PTX)
// ---------------------------------------------------------------------------
__device__ __forceinline__ unsigned long long pk2(float lo, float hi) {
    unsigned long long r;
    asm("mov.b64 %0, {%1, %2};"
        : "=l"(r) : "r"(__float_as_uint(lo)), "r"(__float_as_uint(hi)));
    return r;
}
__device__ __forceinline__ unsigned long long pkdup(float v) {
    unsigned long long r;
    asm("mov.b64 %0, {%1, %1};" : "=l"(r) : "r"(__float_as_uint(v)));
    return r;
}
__device__ __forceinline__ void fma2(unsigned long long& d, unsigned long long a,
                                     unsigned long long b) {
    asm("fma.rn.f32x2 %0, %1, %2, %0;" : "+l"(d) : "l"(a), "l"(b));
}
__device__ __forceinline__ float lo2(unsigned long long v) {
    return __uint_as_float((unsigned)(v & 0xffffffffull));
}
__device__ __forceinline__ float hi2(unsigned long long v) {
    return __uint_as_float((unsigned)(v >> 32));
}

__device__ __forceinline__ float sigf(float x) {
    return 1.0f / (1.0f + expf(-x));
}
__device__ __forceinline__ float tanh_acc(float x) {
    float ax = fabsf(x);
    float e = expf(-2.0f * ax);
    float r = (1.0f - e) / (1.0f + e);
    return copysignf(r, x);
}

// ---------------------------------------------------------------------------
// Repack kernels (run once per launch; make all GEMM SMEM fills linear copies)
// ---------------------------------------------------------------------------
__global__ void prep_wh(const float* __restrict__ wf, const float* __restrict__ wi,
                        const float* __restrict__ wo, const float* __restrict__ wc) {
    const int total = 128 * H_ * 32;
    for (int idx = blockIdx.x * blockDim.x + threadIdx.x; idx < total;
         idx += gridDim.x * blockDim.x) {
        int r = idx & 31;
        int k = (idx >> 5) & (H_ - 1);
        int jt = idx >> 15;
        int g = r & 3;
        int jj = r >> 2;
        int j = jt * 8 + jj;
        const float* w = (g == 0) ? wf : (g == 1) ? wi : (g == 2) ? wo : wc;
        g_Wpk[idx] = w[(size_t)j * H_ + k];
    }
}

__global__ void prep_wx(const float* __restrict__ wf, const float* __restrict__ wi,
                        const float* __restrict__ wo, const float* __restrict__ wc) {
    const int total = 128 * F_ * 32;
    for (int idx = blockIdx.x * blockDim.x + threadIdx.x; idx < total;
         idx += gridDim.x * blockDim.x) {
        int r = idx & 31;
        int k = (idx >> 5) & (F_ - 1);
        int jt = idx >> 13;
        int g = r & 3;
        int jj = r >> 2;
        int j = jt * 8 + jj;
        const float* w = (g == 0) ? wf : (g == 1) ? wi : (g == 2) ? wo : wc;
        g_WXpk[idx] = w[(size_t)j * F_ + k];
    }
}

__global__ void prep_fc(const float* __restrict__ fco_w) {
    const int total = 9 * H_ * 32;
    for (int idx = blockIdx.x * blockDim.x + threadIdx.x; idx < total;
         idx += gridDim.x * blockDim.x) {
        int cc = idx & 31;
        int k = (idx >> 5) & (H_ - 1);
        int ct = idx >> 15;
        int c = ct * 32 + cc;
        g_FCpk[idx] = (c < C_) ? fco_w[(size_t)c * H_ + k] : 0.0f;
    }
}

__global__ void prep_xt(const float* __restrict__ x) {
    const int total = T_ * F_ * B_;
    for (int idx = blockIdx.x * blockDim.x + threadIdx.x; idx < total;
         idx += gridDim.x * blockDim.x) {
        int b = idx & (B_ - 1);
        int k = (idx >> 6) & (F_ - 1);
        int t = idx >> 14;
        g_xT[idx] = x[((size_t)t * B_ + b) * F_ + k];
    }
}

// ---------------------------------------------------------------------------
// GEMM core: CTA tile = 32 rows x 64 cols, K in chunks of 32, 128 threads.
// A: [k][32r] floats (8 float4/k).  B: [k][64b] floats (16 float4/k).
// Thread (tn = tid>>4, tb = tid&15): rows tn*4..+3, cols tb*4..+3.
// Reg-double-buffered SMEM. acc[r][pair] packed f32x2 along columns.
// ---------------------------------------------------------------------------
template <int NK>
__device__ __forceinline__ void gemm_core(const float4* __restrict__ Ag,
                                          const float4* __restrict__ Bg,
                                          float4 (*sA)[256], float4 (*sB)[512],
                                          unsigned long long (&acc)[4][2]) {
    const int tid = threadIdx.x;
    const int tn = tid >> 4;
    const int tb = tid & 15;

    float4 ra0, ra1, rb0, rb1, rb2, rb3;
    // chunk 0 -> smem[0]
    ra0 = Ag[tid];       ra1 = Ag[tid + 128];
    rb0 = Bg[tid];       rb1 = Bg[tid + 128];
    rb2 = Bg[tid + 256]; rb3 = Bg[tid + 384];
    sA[0][tid] = ra0;       sA[0][tid + 128] = ra1;
    sB[0][tid] = rb0;       sB[0][tid + 128] = rb1;
    sB[0][tid + 256] = rb2; sB[0][tid + 384] = rb3;
    __syncthreads();

#pragma unroll 1
    for (int ch = 0; ch < NK; ++ch) {
        const int cur = ch & 1;
        const int nxt = cur ^ 1;
        if (ch + 1 < NK) {
            const float4* An = Ag + (size_t)(ch + 1) * 256;
            const float4* Bn = Bg + (size_t)(ch + 1) * 512;
            ra0 = An[tid];       ra1 = An[tid + 128];
            rb0 = Bn[tid];       rb1 = Bn[tid + 128];
            rb2 = Bn[tid + 256]; rb3 = Bn[tid + 384];
        }
        const float4* A = sA[cur];
        const float4* Bv = sB[cur];
#pragma unroll
        for (int kk = 0; kk < 32; ++kk) {
            float4 a = A[kk * 8 + tn];
            const unsigned long long* bp =
                reinterpret_cast<const unsigned long long*>(&Bv[kk * 16 + tb]);
            unsigned long long b0 = bp[0];
            unsigned long long b1 = bp[1];
            unsigned long long a0 = pkdup(a.x);
            unsigned long long a1 = pkdup(a.y);
            unsigned long long a2 = pkdup(a.z);
            unsigned long long a3 = pkdup(a.w);
            fma2(acc[0][0], a0, b0); fma2(acc[0][1], a0, b1);
            fma2(acc[1][0], a1, b0); fma2(acc[1][1], a1, b1);
            fma2(acc[2][0], a2, b0); fma2(acc[2][1], a2, b1);
            fma2(acc[3][0], a3, b0); fma2(acc[3][1], a3, b1);
        }
        __syncthreads();
        if (ch + 1 < NK) {
            sA[nxt][tid] = ra0;       sA[nxt][tid + 128] = ra1;
            sB[nxt][tid] = rb0;       sB[nxt][tid + 128] = rb1;
            sB[nxt][tid + 256] = rb2; sB[nxt][tid + 384] = rb3;
            __syncthreads();
        }
    }
}

__device__ __forceinline__ void unpack_acc(const unsigned long long (&acc)[4][2],
                                           float (&z)[4][4]) {
#pragma unroll
    for (int r = 0; r < 4; ++r) {
        z[r][0] = lo2(acc[r][0]);
        z[r][1] = hi2(acc[r][0]);
        z[r][2] = lo2(acc[r][1]);
        z[r][3] = hi2(acc[r][1]);
    }
}

// ---------------------------------------------------------------------------
// Input-projection GEMM: gates[t][j][b][g] = x[t][b]:F dot wx[g][j]:F + bias
// grid (128 jt, 512 t), block 128
// ---------------------------------------------------------------------------
__global__ void k_gates(const float* __restrict__ bf, const float* __restrict__ bi,
                        const float* __restrict__ bo, const float* __restrict__ bc) {
    const int jt = blockIdx.x;
    const int t = blockIdx.y;
    __shared__ float4 sA[2][256];
    __shared__ float4 sB[2][512];
    unsigned long long acc[4][2] = {};

    const float4* Ag = reinterpret_cast<const float4*>(g_WXpk) + (size_t)jt * F_ * 8;
    const float4* Bg = reinterpret_cast<const float4*>(g_xT) + (size_t)t * F_ * 16;
    gemm_core<F_ / 32>(Ag, Bg, sA, sB, acc);

    const int tn = threadIdx.x >> 4;
    const int tb = threadIdx.x & 15;
    const int j = jt * 8 + tn;
    float z[4][4];
    unpack_acc(acc, z);
    const float b0 = bf[j], b1 = bi[j], b2 = bo[j], b3 = bc[j];
    float4* G = reinterpret_cast<float4*>(g_gates) + ((size_t)t * H_ + j) * 64 + tb * 4;
#pragma unroll
    for (int bb = 0; bb < 4; ++bb) {
        G[bb] = make_float4(z[0][bb] + b0, z[1][bb] + b1, z[2][bb] + b2, z[3][bb] + b3);
    }
}

// ---------------------------------------------------------------------------
// One recurrence step (fused GEMM + LSTM cell). grid 128, block 128.
// CTA jt covers j = jt*8..+7; each thread owns all 4 gates of one j, 4 b's.
// ---------------------------------------------------------------------------
__global__ void k_step(int t) {
    const int jt = blockIdx.x;
    __shared__ float4 sA[2][256];
    __shared__ float4 sB[2][512];
    unsigned long long acc[4][2] = {};

    if (t > 0) {
        const float4* Ag = reinterpret_cast<const float4*>(g_Wpk) + (size_t)jt * H_ * 8;
        const float4* Bg = reinterpret_cast<const float4*>(g_hT) + (size_t)(t - 1) * H_ * 16;
        gemm_core<H_ / 32>(Ag, Bg, sA, sB, acc);
    }

    const int tn = threadIdx.x >> 4;
    const int tb = threadIdx.x & 15;
    const int j = jt * 8 + tn;

    float z[4][4];
    unpack_acc(acc, z);

    const float4* Gx =
        reinterpret_cast<const float4*>(g_gates) + ((size_t)t * H_ + j) * 64 + tb * 4;
    float4* cp = reinterpret_cast<float4*>(g_cT) + (j * 16 + tb);
    float4 cprev = (t > 0) ? *cp : make_float4(0.f, 0.f, 0.f, 0.f);
    float cpv[4] = {cprev.x, cprev.y, cprev.z, cprev.w};

    float cn[4], hn[4];
#pragma unroll
    for (int bb = 0; bb < 4; ++bb) {
        float4 gx = Gx[bb];
        float zf = z[0][bb] + gx.x;
        float zi = z[1][bb] + gx.y;
        float zo = z[2][bb] + gx.z;
        float za = z[3][bb] + gx.w;
        float ft = sigf(zf);
        float it = sigf(zi);
        float ot = sigf(zo);
        float cv = it * tanh_acc(za) + ft * cpv[bb];
        cn[bb] = cv;
        hn[bb] = ot * tanh_acc(cv);
    }
    *cp = make_float4(cn[0], cn[1], cn[2], cn[3]);
    reinterpret_cast<float4*>(g_hT)[((size_t)t * H_ + j) * 16 + tb] =
        make_float4(hn[0], hn[1], hn[2], hn[3]);
}

// ---------------------------------------------------------------------------
// Output projection: out[t][b][c] = hT[t][:,b] dot fco_w[c,:] + fco_b[c]
// grid (9 ct, 512 t), block 128
// ---------------------------------------------------------------------------
__global__ void k_out(const float* __restrict__ fco_b, float* __restrict__ out) {
    const int ct = blockIdx.x;
    const int t = blockIdx.y;
    __shared__ float4 sA[2][256];
    __shared__ float4 sB[2][512];
    unsigned long long acc[4][2] = {};

    const float4* Ag = reinterpret_cast<const float4*>(g_FCpk) + (size_t)ct * H_ * 8;
    const float4* Bg = reinterpret_cast<const float4*>(g_hT) + (size_t)t * H_ * 16;
    gemm_core<H_ / 32>(Ag, Bg, sA, sB, acc);

    const int tn = threadIdx.x >> 4;
    const int tb = threadIdx.x & 15;
    const int c0 = ct * 32 + tn * 4;

    float z[4][4];
    unpack_acc(acc, z);

#pragma unroll
    for (int bb = 0; bb < 4; ++bb) {
        const int b = tb * 4 + bb;
        float* o = out + ((size_t)t * B_ + b) * C_;
#pragma unroll
        for (int ci = 0; ci < 4; ++ci) {
            const int c = c0 + ci;
            if (c < C_) o[c] = z[ci][bb] + fco_b[c];
        }
    }
}

// ---------------------------------------------------------------------------
// Launch
// ---------------------------------------------------------------------------
extern "C" void kernel_launch(void* const* d_in, const int* in_sizes, int n_in,
                              void* d_out, int out_size) {
    const float* x     = (const float*)d_in[0];
    const float* wfx_w = (const float*)d_in[1];
    const float* wfx_b = (const float*)d_in[2];
    const float* wix_w = (const float*)d_in[3];
    const float* wix_b = (const float*)d_in[4];
    const float* wox_w = (const float*)d_in[5];
    const float* wox_b = (const float*)d_in[6];
    const float* wcx_w = (const float*)d_in[7];
    const float* wcx_b = (const float*)d_in[8];
    const float* wfh_w = (const float*)d_in[9];
    const float* wih_w = (const float*)d_in[10];
    const float* woh_w = (const float*)d_in[11];
    const float* wch_w = (const float*)d_in[12];
    const float* fco_w = (const float*)d_in[13];
    const float* fco_b = (const float*)d_in[14];
    float* out = (float*)d_out;

    (void)in_sizes; (void)n_in; (void)out_size;

    prep_wh<<<4096, 256>>>(wfh_w, wih_w, woh_w, wch_w);
    prep_wx<<<2048, 256>>>(wfx_w, wix_w, wox_w, wcx_w);
    prep_fc<<<576, 256>>>(fco_w);
    prep_xt<<<4096, 256>>>(x);

    k_gates<<<dim3(128, 512), 128>>>(wfx_b, wix_b, wox_b, wcx_b);

    for (int t = 0; t < T_; ++t) {
        k_step<<<128, 128>>>(t);
    }

    k_out<<<dim3(9, 512), 128>>>(fco_b, out);
}